// round 5
// baseline (speedup 1.0000x reference)
#include <cuda_runtime.h>

// Problem shape (fixed by reference setup_inputs)
#define NBATCH 2
#define DD 160
#define HH 192
#define WW 224
#define HHWW (HH * WW)

// Tiling: warp = 32 x-columns by YPT=4 y-rows, rolling in z. No smem, no barriers.
#define TZ 10
#define YPT 4
#define WARPS_Y 4                       // blockDim.y
#define NTHREADS 128
#define YTILE (WARPS_Y * YPT)           // 16
#define GXB (WW / 32)                   // 7
#define GYB (HH / YTILE)                // 12
#define ZCH (DD / TZ)                   // 16
#define GZB (NBATCH * ZCH)              // 32
#define TOTAL_BLOCKS (GXB * GYB * GZB)  // 2688

__device__ double g_partial[TOTAL_BLOCKS];
__device__ unsigned int g_count = 0;    // self-wrapping via atomicInc

// Compute the per-plane column partials for this thread's 4 output rows:
//   A = smooth_x*smooth_y, B = diff_x*smooth_y, C = smooth_x*diff_y
__device__ __forceinline__ void plane_abc(
    const float* __restrict__ xp, const float* __restrict__ yp,
    bool zok, const int* __restrict__ rowoff, const bool* __restrict__ okr,
    int edelta, bool eokx, int lane,
    float A[YPT], float B[YPT], float C[YPT])
{
    float rsx[YPT + 2], rdx[YPT + 2];
#pragma unroll
    for (int k = 0; k < YPT + 2; ++k) {
        const bool o = zok && okr[k];
        const float a = o ? __ldg(xp + rowoff[k]) : 0.f;
        const float b = o ? __ldg(yp + rowoff[k]) : 0.f;
        const bool eo = o && eokx;                       // true only on lanes 0 / 31
        const float ea = eo ? __ldg(xp + rowoff[k] + edelta) : 0.f;
        const float eb = eo ? __ldg(yp + rowoff[k] + edelta) : 0.f;
        const float d0 = a - b;
        const float ed = ea - eb;
        float dm = __shfl_up_sync(0xffffffffu, d0, 1);
        float dp = __shfl_down_sync(0xffffffffu, d0, 1);
        dm = (lane == 0)  ? ed : dm;
        dp = (lane == 31) ? ed : dp;
        rsx[k] = fmaf(2.f, d0, dm + dp);
        rdx[k] = dm - dp;
    }
#pragma unroll
    for (int j = 0; j < YPT; ++j) {
        A[j] = fmaf(2.f, rsx[j + 1], rsx[j] + rsx[j + 2]);
        C[j] = rsx[j] - rsx[j + 2];
        B[j] = fmaf(2.f, rdx[j + 1], rdx[j] + rdx[j + 2]);
    }
}

__global__ void __launch_bounds__(NTHREADS, 7) grad_loss_kernel(
    const float* __restrict__ x, const float* __restrict__ y,
    float* __restrict__ out)
{
    const int lane = threadIdx.x;
    const int wy   = threadIdx.y;
    const int tid  = wy * 32 + lane;

    const int x0    = blockIdx.x * 32;
    const int gx    = x0 + lane;
    const int ybase = blockIdx.y * YTILE + wy * YPT;
    const int bz    = blockIdx.z;
    const int n     = bz / ZCH;
    const int z0    = (bz % ZCH) * TZ;
    const int bid   = blockIdx.x + GXB * (blockIdx.y + GYB * blockIdx.z);

    const float* xb = x + (size_t)n * DD * HHWW;
    const float* yb = y + (size_t)n * DD * HHWW;

    // ---- plane-invariant bookkeeping ----
    int  rowoff[YPT + 2];
    bool okr[YPT + 2];
#pragma unroll
    for (int k = 0; k < YPT + 2; ++k) {
        const int gy = ybase - 1 + k;
        okr[k]    = (gy >= 0) && (gy < HH);
        rowoff[k] = (okr[k] ? gy : 0) * WW + gx;
    }
    const bool isL = (lane == 0), isR = (lane == 31);
    const int  ex   = isL ? (x0 - 1) : (isR ? (x0 + 32) : gx);
    const bool eokx = (isL || isR) && (ex >= 0) && (ex < WW);
    const int  edelta = (eokx ? ex : gx) - gx;   // safe 0 for inactive lanes

    float A2[YPT], B2[YPT], C2[YPT];
    float A1[YPT], B1[YPT], C1[YPT];
    float A0[YPT], B0[YPT], C0[YPT];

    // ---- prologue: planes z0-1 and z0 ----
    {
        const int gz = z0 - 1;
        const bool zok = (gz >= 0);
        const size_t b = (size_t)(zok ? gz : 0) * HHWW;
        plane_abc(xb + b, yb + b, zok, rowoff, okr, edelta, eokx, lane, A2, B2, C2);
    }
    plane_abc(xb + (size_t)z0 * HHWW, yb + (size_t)z0 * HHWW,
              true, rowoff, okr, edelta, eokx, lane, A1, B1, C1);

    float acc = 0.f;

#pragma unroll 3
    for (int p = 2; p < TZ + 2; ++p) {
        const int gz = z0 - 1 + p;             // >= z0+1 >= 1
        const bool zok = (gz < DD);
        const size_t b = (size_t)(zok ? gz : 0) * HHWW;
        plane_abc(xb + b, yb + b, zok, rowoff, okr, edelta, eokx, lane, A0, B0, C0);

#pragma unroll
        for (int j = 0; j < YPT; ++j) {
            const float fx = A2[j] - A0[j];                      // diff_z(A)
            const float fy = fmaf(2.f, C1[j], C2[j] + C0[j]);    // smooth_z(C)
            const float fz = fmaf(2.f, B1[j], B2[j] + B0[j]);    // smooth_z(B)
            acc = fmaf(fx, fx, acc);
            acc = fmaf(fy, fy, acc);
            acc = fmaf(fz, fz, acc);
            A2[j] = A1[j]; A1[j] = A0[j];
            B2[j] = B1[j]; B1[j] = B0[j];
            C2[j] = C1[j]; C1[j] = C0[j];
        }
    }

    // ---- block reduction (deterministic order) ----
#pragma unroll
    for (int o = 16; o; o >>= 1)
        acc += __shfl_down_sync(0xffffffffu, acc, o);

    __shared__ float warpsum[WARPS_Y];
    __shared__ bool  s_last;
    if (lane == 0) warpsum[wy] = acc;
    __syncthreads();
    if (tid == 0) {
        float s = 0.f;
#pragma unroll
        for (int w = 0; w < WARPS_Y; ++w) s += warpsum[w];
        g_partial[bid] = (double)s;
        __threadfence();
        const unsigned old = atomicInc(&g_count, TOTAL_BLOCKS - 1); // wraps to 0
        s_last = (old == TOTAL_BLOCKS - 1);
    }
    __syncthreads();

    // ---- last block: sum partials, write scalar output ----
    if (s_last) {
        double ds = 0.0;
        for (int i = tid; i < TOTAL_BLOCKS; i += NTHREADS)
            ds += g_partial[i];
#pragma unroll
        for (int o = 16; o; o >>= 1)
            ds += __shfl_down_sync(0xffffffffu, ds, o);
        __shared__ double dwarp[WARPS_Y];
        if (lane == 0) dwarp[wy] = ds;
        __syncthreads();
        if (tid == 0) {
            double t = 0.0;
#pragma unroll
            for (int w = 0; w < WARPS_Y; ++w) t += dwarp[w];
            out[0] = (float)(t / ((double)NBATCH * DD * HH * WW));
        }
    }
}

extern "C" void kernel_launch(void* const* d_in, const int* in_sizes, int n_in,
                              void* d_out, int out_size)
{
    const float* x = (const float*)d_in[0];
    const float* y = (const float*)d_in[1];
    float* out = (float*)d_out;

    dim3 block(32, WARPS_Y, 1);      // 128 threads
    dim3 grid(GXB, GYB, GZB);        // 7 x 12 x 32 = 2688
    grad_loss_kernel<<<grid, block>>>(x, y, out);
}

// round 6
// speedup vs baseline: 2.0741x; 2.0741x over previous
#include <cuda_runtime.h>

// Problem shape (fixed by reference setup_inputs)
#define NBATCH 2
#define DD 160
#define HH 192
#define WW 224
#define HHWW (HH * WW)

// Tiling: thread = 4 consecutive x-pixels (float4), block tile 32x16, rolling z.
#define TX 32
#define TY 16
#define TZ 32
#define NTX 8                    // blockDim.x (8 * 4 = 32 x-pixels)
#define NTHREADS 128
#define HROWS (TY + 2)           // 18
#define VROW 10                  // float4 per smem row: [x0-4, x0+36)
#define SROW (VROW * 4)          // 40 floats
#define VEC_ELEMS (HROWS * VROW) // 180
#define GXB (WW / TX)            // 7
#define GYB (HH / TY)            // 12
#define GZB (NBATCH * (DD / TZ)) // 10
#define TOTAL_BLOCKS (GXB * GYB * GZB)  // 840

__device__ double g_partial[TOTAL_BLOCKS];
__device__ unsigned int g_count = 0;   // self-wrapping via atomicInc

__global__ void __launch_bounds__(NTHREADS) grad_loss_kernel(
    const float* __restrict__ x, const float* __restrict__ y,
    float* __restrict__ out)
{
    __shared__ float sd[2][HROWS][SROW];   // double-buffered (x-y) diff plane

    const int txq = threadIdx.x;           // 0..7
    const int ty  = threadIdx.y;           // 0..15
    const int tid = ty * NTX + txq;

    const int x0 = blockIdx.x * TX;
    const int y0 = blockIdx.y * TY;
    const int bz = blockIdx.z;
    const int n  = bz / (DD / TZ);
    const int z0 = (bz % (DD / TZ)) * TZ;
    const int bid = blockIdx.x + GXB * (blockIdx.y + GYB * blockIdx.z);

    const float* xb = x + (size_t)n * DD * HHWW;
    const float* yb = y + (size_t)n * DD * HHWW;

    // ---- plane-invariant halo-load bookkeeping (2 predicated float4 slots) ----
    // Every float4 in the halo plane is either fully valid or fully zero:
    // x-halo is exactly one float4 per side ([x0-4,x0) / [x0+32,x0+36)).
    int  goff[2], soff[2];
    bool ok2[2];
#pragma unroll
    for (int i = 0; i < 2; ++i) {
        const int idx = tid + i * NTHREADS;
        const int r   = idx / VROW;
        const int c   = idx - r * VROW;
        const int gy  = y0 - 1 + r;
        const int gxb = x0 - 4 + 4 * c;
        const bool v  = (idx < VEC_ELEMS) &&
                        (gy >= 0) && (gy < HH) && (gxb >= 0) && (gxb + 3 < WW);
        ok2[i]  = v;
        goff[i] = v ? (gy * WW + gxb) : 0;
        soff[i] = r * SROW + 4 * c;
    }
    const bool act1 = (tid + NTHREADS < VEC_ELEMS);

    // Rolling z-state per output column (4 cols): A=sx*sy, B=dx*sy, C=sx*dy
    float A2[4], A1[4], B2[4], B1[4], C2[4], C1[4];
#pragma unroll
    for (int c = 0; c < 4; ++c)
        A2[c] = A1[c] = B2[c] = B1[c] = C2[c] = C1[c] = 0.f;
    float acc = 0.f;

    // ---- prologue: load plane gz = z0-1 into buffer 0 ----
    {
        const int gz = z0 - 1;
        const bool zok = (gz >= 0);
        const float* xp = xb + (size_t)(zok ? gz : 0) * HHWW;
        const float* yp = yb + (size_t)(zok ? gz : 0) * HHWW;
#pragma unroll
        for (int i = 0; i < 2; ++i) {
            const bool o = zok && ok2[i];
            float4 d = make_float4(0.f, 0.f, 0.f, 0.f);
            if (o) {
                const float4 a = __ldg((const float4*)(xp + goff[i]));
                const float4 b = __ldg((const float4*)(yp + goff[i]));
                d = make_float4(a.x - b.x, a.y - b.y, a.z - b.z, a.w - b.w);
            }
            if (i == 0 || act1)
                *(float4*)(&sd[0][0][0] + soff[i]) = d;
        }
    }
    __syncthreads();

    const int lc = 4 + 4 * txq;   // smem col of this thread's first output pixel

    for (int p = 0; p < TZ + 2; ++p) {
        // ---- (a) issue prefetch LDGs for plane gz = z0 + p ----
        float4 v0 = make_float4(0.f, 0.f, 0.f, 0.f);
        float4 v1 = make_float4(0.f, 0.f, 0.f, 0.f);
        const bool haveNext = (p <= TZ);
        if (haveNext) {
            const int gz = z0 + p;
            const bool zok = (gz < DD);
            const float* xp = xb + (size_t)(zok ? gz : 0) * HHWW;
            const float* yp = yb + (size_t)(zok ? gz : 0) * HHWW;
            if (zok && ok2[0]) {
                const float4 a = __ldg((const float4*)(xp + goff[0]));
                const float4 b = __ldg((const float4*)(yp + goff[0]));
                v0 = make_float4(a.x - b.x, a.y - b.y, a.z - b.z, a.w - b.w);
            }
            if (zok && ok2[1]) {
                const float4 a = __ldg((const float4*)(xp + goff[1]));
                const float4 b = __ldg((const float4*)(yp + goff[1]));
                v1 = make_float4(a.x - b.x, a.y - b.y, a.z - b.z, a.w - b.w);
            }
        }

        // ---- (b) compute plane p from buffer p&1 (overlaps prefetch) ----
        const int bsel = p & 1;
        float rsx[3][4], rdx[3][4];
#pragma unroll
        for (int k = 0; k < 3; ++k) {
            const float* row = &sd[bsel][ty + k][0];
            const float4 d = *(const float4*)(row + lc);
            const float dl = row[lc - 1];
            const float dr = row[lc + 4];
            // d[-1]=dl, d0..d3, d[4]=dr
            rsx[k][0] = fmaf(2.f, d.x, dl + d.y);
            rsx[k][1] = fmaf(2.f, d.y, d.x + d.z);
            rsx[k][2] = fmaf(2.f, d.z, d.y + d.w);
            rsx[k][3] = fmaf(2.f, d.w, d.z + dr);
            rdx[k][0] = dl - d.y;
            rdx[k][1] = d.x - d.z;
            rdx[k][2] = d.y - d.w;
            rdx[k][3] = d.z - dr;
        }
#pragma unroll
        for (int c = 0; c < 4; ++c) {
            const float A = fmaf(2.f, rsx[1][c], rsx[0][c] + rsx[2][c]);
            const float C = rsx[0][c] - rsx[2][c];
            const float B = fmaf(2.f, rdx[1][c], rdx[0][c] + rdx[2][c]);

            if (p >= 2) {   // emit output for plane z0 + p - 2
                const float fx = A2[c] - A;                     // diff_z(A)
                const float fy = fmaf(2.f, C1[c], C2[c] + C);   // smooth_z(C)
                const float fz = fmaf(2.f, B1[c], B2[c] + B);   // smooth_z(B)
                acc = fmaf(fx, fx, acc);
                acc = fmaf(fy, fy, acc);
                acc = fmaf(fz, fz, acc);
            }
            A2[c] = A1[c]; A1[c] = A;
            B2[c] = B1[c]; B1[c] = B;
            C2[c] = C1[c]; C1[c] = C;
        }

        // ---- (c) store prefetched plane into other buffer ----
        if (haveNext) {
            float* sn = &sd[bsel ^ 1][0][0];
            *(float4*)(sn + soff[0]) = v0;
            if (act1) *(float4*)(sn + soff[1]) = v1;
        }
        __syncthreads();
    }

    // ---- block reduction (deterministic order) ----
#pragma unroll
    for (int o = 16; o; o >>= 1)
        acc += __shfl_down_sync(0xffffffffu, acc, o);

    __shared__ float warpsum[4];
    __shared__ bool  s_last;
    const int wid  = tid >> 5;
    const int lane = tid & 31;
    if (lane == 0) warpsum[wid] = acc;
    __syncthreads();
    if (tid == 0) {
        float s = 0.f;
#pragma unroll
        for (int w = 0; w < 4; ++w) s += warpsum[w];
        g_partial[bid] = (double)s;
        __threadfence();
        const unsigned old = atomicInc(&g_count, TOTAL_BLOCKS - 1); // wraps to 0
        s_last = (old == TOTAL_BLOCKS - 1);
    }
    __syncthreads();

    // ---- last block: sum partials, write scalar output ----
    if (s_last) {
        double ds = 0.0;
        for (int i = tid; i < TOTAL_BLOCKS; i += NTHREADS)
            ds += g_partial[i];
#pragma unroll
        for (int o = 16; o; o >>= 1)
            ds += __shfl_down_sync(0xffffffffu, ds, o);
        __shared__ double dwarp[4];
        if (lane == 0) dwarp[wid] = ds;
        __syncthreads();
        if (tid == 0) {
            double t = 0.0;
#pragma unroll
            for (int w = 0; w < 4; ++w) t += dwarp[w];
            out[0] = (float)(t / ((double)NBATCH * DD * HH * WW));
        }
    }
}

extern "C" void kernel_launch(void* const* d_in, const int* in_sizes, int n_in,
                              void* d_out, int out_size)
{
    const float* x = (const float*)d_in[0];
    const float* y = (const float*)d_in[1];
    float* out = (float*)d_out;

    dim3 block(NTX, TY, 1);          // 8 x 16 = 128 threads
    dim3 grid(GXB, GYB, GZB);        // 7 x 12 x 10 = 840
    grad_loss_kernel<<<grid, block>>>(x, y, out);
}